// round 4
// baseline (speedup 1.0000x reference)
#include <cuda_runtime.h>
#include <cuda_bf16.h>
#include <cstdint>

#define XP 136   // bf16 pitch, x tiles [d][n]
#define AP 136   // bf16 pitch, A tiles [k][n]
#define CP 136   // bf16 pitch, codeword tile [k][d]
#define SP 130   // fp32 pitch, sl tile [k][n]

struct Sm {
    __nv_bfloat16 xhi[128 * XP];
    __nv_bfloat16 xlo[128 * XP];
    __nv_bfloat16 chi[32 * CP];
    __nv_bfloat16 ahi[32 * AP];
    __nv_bfloat16 alo[32 * AP];
    float slA[32 * SP];      // aliased as x2p (8*128) during load phase
    float x2[128];
    float red[512];          // softmax (m,s) exchange; then S_k partials
    float c2[32], scl[32], S[32];
};

static __device__ __forceinline__ uint32_t sptr(const void* p) {
    return (uint32_t)__cvta_generic_to_shared(p);
}
static __device__ __forceinline__ void ldsm4(uint32_t* r, uint32_t a) {
    asm volatile("ldmatrix.sync.aligned.m8n8.x4.shared.b16 {%0,%1,%2,%3},[%4];"
                 : "=r"(r[0]), "=r"(r[1]), "=r"(r[2]), "=r"(r[3]) : "r"(a));
}
static __device__ __forceinline__ void ldsm4t(uint32_t* r, uint32_t a) {
    asm volatile("ldmatrix.sync.aligned.m8n8.x4.trans.shared.b16 {%0,%1,%2,%3},[%4];"
                 : "=r"(r[0]), "=r"(r[1]), "=r"(r[2]), "=r"(r[3]) : "r"(a));
}
static __device__ __forceinline__ void mma16816(float* c, const uint32_t* a, const uint32_t* b) {
    asm volatile(
        "mma.sync.aligned.m16n8k16.row.col.f32.bf16.bf16.f32 "
        "{%0,%1,%2,%3},{%4,%5,%6,%7},{%8,%9},{%0,%1,%2,%3};"
        : "+f"(c[0]), "+f"(c[1]), "+f"(c[2]), "+f"(c[3])
        : "r"(a[0]), "r"(a[1]), "r"(a[2]), "r"(a[3]), "r"(b[0]), "r"(b[1]));
}

__global__ void __launch_bounds__(256, 2)
enc_kernel(const float* __restrict__ X, const float* __restrict__ Cg,
           const float* __restrict__ scaleg, float* __restrict__ out)
{
    extern __shared__ char raw[];
    Sm& s = *reinterpret_cast<Sm*>(raw);
    const int tid = threadIdx.x, lane = tid & 31, w = tid >> 5;
    const int g = lane >> 2, t = lane & 3;
    const int lr = lane & 15, lh = lane >> 4;
    const int brow = (lane >> 4) * 8 + (lane & 7);
    const int bcol = ((lane >> 3) & 1) * 8;
    const int b = blockIdx.y, ch = blockIdx.x;
    const float* Xb = X + (size_t)b * 128 * 16384;

    for (int i = tid; i < 32 * 128; i += 256) {
        int k = i >> 7, d = i & 127;
        s.chi[k * CP + d] = __float2bfloat16(Cg[i]);
    }
    if (tid < 32) {
        float c2 = 0.f;
        #pragma unroll 8
        for (int d = 0; d < 128; d++) { float c = Cg[tid * 128 + d]; c2 += c * c; }
        s.c2[tid] = c2;
        s.scl[tid] = scaleg[tid];
        s.S[tid] = 0.f;
    }

    float e[4][4];
    #pragma unroll
    for (int j = 0; j < 4; j++) { e[j][0] = 0.f; e[j][1] = 0.f; e[j][2] = 0.f; e[j][3] = 0.f; }

    const int mk = (w >> 2) * 16;
    const int jb = (w & 3) * 4;
    const int sn = tid & 127, kh = tid >> 7;   // softmax: n, k-half

    for (int st = 0; st < 8; st++) {
        __syncthreads();
        const int n0 = ch * 1024 + st * 128;

        // ---- load X, split bf16 hi/lo, x2 partials (x2p aliases slA) ----
        {
            float* x2p = s.slA;
            const int nl = lane * 4;
            float p0 = 0.f, p1 = 0.f, p2 = 0.f, p3 = 0.f;
            #pragma unroll
            for (int i = 0; i < 16; i++) {
                const int d = w * 16 + i;
                float4 v = *reinterpret_cast<const float4*>(Xb + (size_t)d * 16384 + n0 + nl);
                __nv_bfloat16 h0 = __float2bfloat16(v.x), h1 = __float2bfloat16(v.y);
                __nv_bfloat16 h2 = __float2bfloat16(v.z), h3 = __float2bfloat16(v.w);
                uint32_t H0 = ((uint32_t)*(uint16_t*)&h0) | ((uint32_t)*(uint16_t*)&h1 << 16);
                uint32_t H1 = ((uint32_t)*(uint16_t*)&h2) | ((uint32_t)*(uint16_t*)&h3 << 16);
                __nv_bfloat16 l0 = __float2bfloat16(v.x - __bfloat162float(h0));
                __nv_bfloat16 l1 = __float2bfloat16(v.y - __bfloat162float(h1));
                __nv_bfloat16 l2 = __float2bfloat16(v.z - __bfloat162float(h2));
                __nv_bfloat16 l3 = __float2bfloat16(v.w - __bfloat162float(h3));
                uint32_t L0 = ((uint32_t)*(uint16_t*)&l0) | ((uint32_t)*(uint16_t*)&l1 << 16);
                uint32_t L1 = ((uint32_t)*(uint16_t*)&l2) | ((uint32_t)*(uint16_t*)&l3 << 16);
                *reinterpret_cast<uint2*>(&s.xhi[d * XP + nl]) = make_uint2(H0, H1);
                *reinterpret_cast<uint2*>(&s.xlo[d * XP + nl]) = make_uint2(L0, L1);
                p0 += v.x * v.x; p1 += v.y * v.y; p2 += v.z * v.z; p3 += v.w * v.w;
            }
            *reinterpret_cast<float4*>(&x2p[w * 128 + nl]) = make_float4(p0, p1, p2, p3);
        }
        __syncthreads();

        if (tid < 128) {
            const float* x2p = s.slA;
            float sum = 0.f;
            #pragma unroll
            for (int q = 0; q < 8; q++) sum += x2p[q * 128 + tid];
            s.x2[tid] = sum;
        }

        // ---- GEMM1 (single pass): xc^T[k][n] = C_hi * X_hi ----
        float acc1[4][4];
        #pragma unroll
        for (int j = 0; j < 4; j++) { acc1[j][0] = 0.f; acc1[j][1] = 0.f; acc1[j][2] = 0.f; acc1[j][3] = 0.f; }
        #pragma unroll
        for (int kd = 0; kd < 8; kd++) {
            const int d0 = kd * 16;
            uint32_t ah[4];
            ldsm4(ah, sptr(&s.chi[(mk + lr) * CP + d0 + lh * 8]));
            #pragma unroll
            for (int jp = 0; jp < 2; jp++) {
                const int nc = (jb + jp * 2) * 8;
                uint32_t bh[4];
                ldsm4t(bh, sptr(&s.xhi[(d0 + lr) * XP + nc + lh * 8]));
                mma16816(acc1[jp * 2 + 0], ah, bh + 0);
                mma16816(acc1[jp * 2 + 1], ah, bh + 2);
            }
        }
        __syncthreads();   // x2 ready; x2p dead -> slA writable

        #pragma unroll
        for (int j = 0; j < 4; j++) {
            const int nn = (jb + j) * 8 + 2 * t;
            const int k0 = mk + g, k1 = mk + g + 8;
            s.slA[k0 * SP + nn]     = s.scl[k0] * (s.x2[nn]     - 2.f * acc1[j][0] + s.c2[k0]);
            s.slA[k0 * SP + nn + 1] = s.scl[k0] * (s.x2[nn + 1] - 2.f * acc1[j][1] + s.c2[k0]);
            s.slA[k1 * SP + nn]     = s.scl[k1] * (s.x2[nn]     - 2.f * acc1[j][2] + s.c2[k1]);
            s.slA[k1 * SP + nn + 1] = s.scl[k1] * (s.x2[nn + 1] - 2.f * acc1[j][3] + s.c2[k1]);
        }
        __syncthreads();

        // ---- softmax phase A: each thread does 16 k's for n=sn ----
        {
            const int kb = kh * 16;
            float v[16];
            float m = -1e30f;
            #pragma unroll
            for (int k = 0; k < 16; k++) { v[k] = s.slA[(kb + k) * SP + sn]; m = fmaxf(m, v[k]); }
            float sum = 0.f;
            #pragma unroll
            for (int k = 0; k < 16; k++) { v[k] = __expf(v[k] - m); sum += v[k]; }
            #pragma unroll
            for (int k = 0; k < 16; k++) s.slA[(kb + k) * SP + sn] = v[k];
            s.red[kh * 128 + sn] = m;
            s.red[256 + kh * 128 + sn] = sum;
        }
        __syncthreads();

        // ---- softmax phase B: combine halves, normalize, write A hi/lo + fp32 ----
        {
            const int kb = kh * 16;
            const float m  = s.red[kh * 128 + sn];
            const float so = s.red[256 + (kh ^ 1) * 128 + sn];
            const float mo = s.red[(kh ^ 1) * 128 + sn];
            const float sm = s.red[256 + kh * 128 + sn];
            const float M = fmaxf(m, mo);
            const float cm = __expf(m - M), co = __expf(mo - M);
            const float f = cm / (sm * cm + so * co);
            #pragma unroll
            for (int k = 0; k < 16; k++) {
                float a = s.slA[(kb + k) * SP + sn] * f;
                __nv_bfloat16 h = __float2bfloat16(a);
                s.ahi[(kb + k) * AP + sn] = h;
                s.alo[(kb + k) * AP + sn] = __float2bfloat16(a - __bfloat162float(h));
                s.slA[(kb + k) * SP + sn] = a;
            }
        }
        __syncthreads();

        // ---- S_k partials (into red) ----
        {
            const int k = tid >> 3, seg = tid & 7;
            const float* p = &s.slA[k * SP + seg * 16];
            float sum = 0.f;
            #pragma unroll
            for (int i = 0; i < 16; i++) sum += p[i];
            s.red[k * 8 + seg] = sum;
        }
        __syncthreads();
        if (tid < 32) {
            float ss = 0.f;
            #pragma unroll
            for (int q = 0; q < 8; q++) ss += s.red[tid * 8 + q];
            s.S[tid] += ss;
        }

        // ---- GEMM2: E^T[d][k] += X_hi*A_hi + X_hi*A_lo + X_lo*A_hi ----
        #pragma unroll
        for (int kn = 0; kn < 8; kn++) {
            const int nn = kn * 16;
            uint32_t xh[4], xl[4];
            ldsm4(xh, sptr(&s.xhi[(16 * w + lr) * XP + nn + lh * 8]));
            ldsm4(xl, sptr(&s.xlo[(16 * w + lr) * XP + nn + lh * 8]));
            uint32_t b0h[4], b0l[4], b1h[4], b1l[4];
            ldsm4(b0h, sptr(&s.ahi[brow * AP + nn + bcol]));
            ldsm4(b0l, sptr(&s.alo[brow * AP + nn + bcol]));
            ldsm4(b1h, sptr(&s.ahi[(16 + brow) * AP + nn + bcol]));
            ldsm4(b1l, sptr(&s.alo[(16 + brow) * AP + nn + bcol]));
            mma16816(e[0], xh, b0h + 0); mma16816(e[0], xh, b0l + 0); mma16816(e[0], xl, b0h + 0);
            mma16816(e[1], xh, b0h + 2); mma16816(e[1], xh, b0l + 2); mma16816(e[1], xl, b0h + 2);
            mma16816(e[2], xh, b1h + 0); mma16816(e[2], xh, b1l + 0); mma16816(e[2], xl, b1h + 0);
            mma16816(e[3], xh, b1h + 2); mma16816(e[3], xh, b1l + 2); mma16816(e[3], xl, b1h + 2);
        }
    }

    __syncthreads();

    float* outb = out + (size_t)b * 32 * 128;
    #pragma unroll
    for (int j = 0; j < 4; j++) {
        const int k0 = j * 8 + 2 * t, d0 = 16 * w + g;
        atomicAdd(&outb[k0 * 128 + d0],           e[j][0] - s.S[k0]     * Cg[k0 * 128 + d0]);
        atomicAdd(&outb[(k0 + 1) * 128 + d0],     e[j][1] - s.S[k0 + 1] * Cg[(k0 + 1) * 128 + d0]);
        atomicAdd(&outb[k0 * 128 + d0 + 8],       e[j][2] - s.S[k0]     * Cg[k0 * 128 + d0 + 8]);
        atomicAdd(&outb[(k0 + 1) * 128 + d0 + 8], e[j][3] - s.S[k0 + 1] * Cg[(k0 + 1) * 128 + d0 + 8]);
    }
}

extern "C" void kernel_launch(void* const* d_in, const int* in_sizes, int n_in,
                              void* d_out, int out_size) {
    const float* X  = (const float*)d_in[0];
    const float* C  = (const float*)d_in[1];
    const float* sc = (const float*)d_in[2];
    float* out = (float*)d_out;

    cudaFuncSetAttribute(enc_kernel, cudaFuncAttributeMaxDynamicSharedMemorySize,
                         (int)sizeof(Sm));
    cudaMemsetAsync(out, 0, (size_t)out_size * sizeof(float));
    dim3 grid(16, 32);
    enc_kernel<<<grid, 256, sizeof(Sm)>>>(X, C, sc, out);
}

// round 5
// speedup vs baseline: 1.2058x; 1.2058x over previous
#include <cuda_runtime.h>
#include <cuda_bf16.h>
#include <cstdint>

#define XP 136
#define AP 136
#define CP 136
#define SP 130

struct Sm {
    __nv_bfloat16 xhi[2][128 * XP];
    __nv_bfloat16 xlo[2][128 * XP];
    __nv_bfloat16 chi[32 * CP];
    __nv_bfloat16 ahi[32 * AP];
    __nv_bfloat16 alo[32 * AP];
    float slA[32 * SP];
    float x2[2][128];
    float x2p[512];
    float Spart[128];
    float c2[32], scl[32];
};

static __device__ __forceinline__ uint32_t sptr(const void* p) {
    return (uint32_t)__cvta_generic_to_shared(p);
}
static __device__ __forceinline__ void ldsm4(uint32_t* r, uint32_t a) {
    asm volatile("ldmatrix.sync.aligned.m8n8.x4.shared.b16 {%0,%1,%2,%3},[%4];"
                 : "=r"(r[0]), "=r"(r[1]), "=r"(r[2]), "=r"(r[3]) : "r"(a));
}
static __device__ __forceinline__ void ldsm4t(uint32_t* r, uint32_t a) {
    asm volatile("ldmatrix.sync.aligned.m8n8.x4.trans.shared.b16 {%0,%1,%2,%3},[%4];"
                 : "=r"(r[0]), "=r"(r[1]), "=r"(r[2]), "=r"(r[3]) : "r"(a));
}
static __device__ __forceinline__ void mma16816(float* c, const uint32_t* a, const uint32_t* b) {
    asm volatile(
        "mma.sync.aligned.m16n8k16.row.col.f32.bf16.bf16.f32 "
        "{%0,%1,%2,%3},{%4,%5,%6,%7},{%8,%9},{%0,%1,%2,%3};"
        : "+f"(c[0]), "+f"(c[1]), "+f"(c[2]), "+f"(c[3])
        : "r"(a[0]), "r"(a[1]), "r"(a[2]), "r"(a[3]), "r"(b[0]), "r"(b[1]));
}
static __device__ __forceinline__ void barsync(int id, int cnt) {
    asm volatile("bar.sync %0, %1;" :: "r"(id), "r"(cnt) : "memory");
}
static __device__ __forceinline__ void bararrive(int id, int cnt) {
    asm volatile("bar.arrive %0, %1;" :: "r"(id), "r"(cnt) : "memory");
}

// barriers: EMPTY0/1 = 2/3, phase = 4, producer-internal = 5, FULL0/1 = 6/7

__global__ void __launch_bounds__(512, 1)
enc_kernel(const float* __restrict__ X, const float* __restrict__ Cg,
           const float* __restrict__ scaleg, float* __restrict__ out)
{
    extern __shared__ char raw[];
    Sm& s = *reinterpret_cast<Sm*>(raw);
    const int tid = threadIdx.x, lane = tid & 31, w = tid >> 5;

    for (int i = tid; i < 4096; i += 512) {
        int k = i >> 7, d = i & 127;
        s.chi[k * CP + d] = __float2bfloat16(Cg[i]);
    }
    if (tid < 32) {
        float c2 = 0.f;
        #pragma unroll 8
        for (int d = 0; d < 128; d++) { float c = Cg[tid * 128 + d]; c2 += c * c; }
        s.c2[tid] = c2;
        s.scl[tid] = scaleg[tid];
    }
    __syncthreads();

    if (w < 4) {
        // ================= PRODUCER (warps 0-3, tid 0..127) =================
        int p = 0;
        const int nl = lane * 4;
        for (int u = blockIdx.x; u < 1024; u += gridDim.x) {
            const float* Xb = X + (size_t)(u >> 5) * (128 * 16384);
            const int chn = (u & 31) * 512;
            for (int st = 0; st < 4; st++) {
                const int n0 = chn + st * 128;
                barsync(2 + p, 512);                       // wait buffer empty
                __nv_bfloat16* xh = s.xhi[p];
                __nv_bfloat16* xl = s.xlo[p];
                float p0 = 0.f, p1 = 0.f, p2 = 0.f, p3 = 0.f;
                #pragma unroll 8
                for (int i = 0; i < 32; i++) {
                    const int d = w * 32 + i;
                    float4 v = *reinterpret_cast<const float4*>(Xb + (size_t)d * 16384 + n0 + nl);
                    __nv_bfloat162 H0 = __floats2bfloat162_rn(v.x, v.y);
                    __nv_bfloat162 H1 = __floats2bfloat162_rn(v.z, v.w);
                    float2 h0f = __bfloat1622float2(H0);
                    float2 h1f = __bfloat1622float2(H1);
                    __nv_bfloat162 L0 = __floats2bfloat162_rn(v.x - h0f.x, v.y - h0f.y);
                    __nv_bfloat162 L1 = __floats2bfloat162_rn(v.z - h1f.x, v.w - h1f.y);
                    *reinterpret_cast<__nv_bfloat162*>(&xh[d * XP + nl])     = H0;
                    *reinterpret_cast<__nv_bfloat162*>(&xh[d * XP + nl + 2]) = H1;
                    *reinterpret_cast<__nv_bfloat162*>(&xl[d * XP + nl])     = L0;
                    *reinterpret_cast<__nv_bfloat162*>(&xl[d * XP + nl + 2]) = L1;
                    p0 = fmaf(v.x, v.x, p0); p1 = fmaf(v.y, v.y, p1);
                    p2 = fmaf(v.z, v.z, p2); p3 = fmaf(v.w, v.w, p3);
                }
                *reinterpret_cast<float4*>(&s.x2p[w * 128 + nl]) = make_float4(p0, p1, p2, p3);
                barsync(5, 128);
                s.x2[p][tid] = s.x2p[tid] + s.x2p[128 + tid] + s.x2p[256 + tid] + s.x2p[384 + tid];
                __threadfence_block();
                bararrive(6 + p, 512);                     // signal buffer full
                p ^= 1;
            }
        }
    } else {
        // ================= CONSUMER (warps 4-15, tid 128..511) =================
        bararrive(2, 512);                                  // prime EMPTY0/1
        bararrive(3, 512);
        const bool heavy = (w < 12);
        const int hw = w - 4;
        const int g = lane >> 2, t = lane & 3;
        const int lr = lane & 15, lh = lane >> 4;
        const int brow = (lane >> 4) * 8 + (lane & 7);
        const int bcol = ((lane >> 3) & 1) * 8;
        const int mk = (hw >> 2) * 16, jb = (hw & 3) * 4;
        const int ctid = tid - 128;                        // heavy: 0..255
        const int sn = ctid >> 1, kh = ctid & 1, kb = kh * 16;
        const int lslot = tid - 384;                       // light: 0..127
        const int kL = lslot & 31, segL = lslot >> 5;
        float sc0 = 0.f, sc1 = 0.f, cc0 = 0.f, cc1 = 0.f;
        if (heavy) {
            sc0 = s.scl[mk + g];     cc0 = s.c2[mk + g];
            sc1 = s.scl[mk + g + 8]; cc1 = s.c2[mk + g + 8];
        }
        float e[4][4];
        #pragma unroll
        for (int j = 0; j < 4; j++) { e[j][0] = 0.f; e[j][1] = 0.f; e[j][2] = 0.f; e[j][3] = 0.f; }
        float Sreg = 0.f;
        int p = 0;
        for (int u = blockIdx.x; u < 1024; u += gridDim.x) {
            for (int st = 0; st < 4; st++) {
                barsync(6 + p, 512);                       // wait buffer full
                if (heavy) {
                    // ---- GEMM1 + sl write ----
                    float acc1[4][4];
                    #pragma unroll
                    for (int j = 0; j < 4; j++) { acc1[j][0] = 0.f; acc1[j][1] = 0.f; acc1[j][2] = 0.f; acc1[j][3] = 0.f; }
                    const __nv_bfloat16* xh = s.xhi[p];
                    #pragma unroll
                    for (int kd = 0; kd < 8; kd++) {
                        const int d0 = kd * 16;
                        uint32_t ah[4];
                        ldsm4(ah, sptr(&s.chi[(mk + lr) * CP + d0 + lh * 8]));
                        #pragma unroll
                        for (int jp = 0; jp < 2; jp++) {
                            const int nc = (jb + jp * 2) * 8;
                            uint32_t bh[4];
                            ldsm4t(bh, sptr(&xh[(d0 + lr) * XP + nc + lh * 8]));
                            mma16816(acc1[jp * 2 + 0], ah, bh + 0);
                            mma16816(acc1[jp * 2 + 1], ah, bh + 2);
                        }
                    }
                    const float* x2 = s.x2[p];
                    #pragma unroll
                    for (int j = 0; j < 4; j++) {
                        const int nn = (jb + j) * 8 + 2 * t;
                        const int k0 = mk + g, k1 = mk + g + 8;
                        s.slA[k0 * SP + nn]     = sc0 * (x2[nn]     - 2.f * acc1[j][0] + cc0);
                        s.slA[k0 * SP + nn + 1] = sc0 * (x2[nn + 1] - 2.f * acc1[j][1] + cc0);
                        s.slA[k1 * SP + nn]     = sc1 * (x2[nn]     - 2.f * acc1[j][2] + cc1);
                        s.slA[k1 * SP + nn + 1] = sc1 * (x2[nn + 1] - 2.f * acc1[j][3] + cc1);
                    }
                }
                barsync(4, 384);
                if (heavy) {
                    // ---- softmax (2 threads per n, halves merged via shfl) ----
                    float v[16];
                    float m = -1e30f;
                    #pragma unroll
                    for (int k = 0; k < 16; k++) { v[k] = s.slA[(kb + k) * SP + sn]; m = fmaxf(m, v[k]); }
                    float sum = 0.f;
                    #pragma unroll
                    for (int k = 0; k < 16; k++) { v[k] = __expf(v[k] - m); sum += v[k]; }
                    const float mo = __shfl_xor_sync(0xffffffffu, m, 1);
                    const float so = __shfl_xor_sync(0xffffffffu, sum, 1);
                    const float M = fmaxf(m, mo);
                    const float cm = __expf(m - M), co = __expf(mo - M);
                    const float f = cm / (sum * cm + so * co);
                    #pragma unroll
                    for (int k = 0; k < 16; k++) {
                        float a = v[k] * f;
                        __nv_bfloat16 h = __float2bfloat16(a);
                        s.ahi[(kb + k) * AP + sn] = h;
                        s.alo[(kb + k) * AP + sn] = __float2bfloat16(a - __bfloat162float(h));
                    }
                }
                barsync(4, 384);
                if (heavy) {
                    // ---- GEMM2 ----
                    const __nv_bfloat16* xh = s.xhi[p];
                    const __nv_bfloat16* xl = s.xlo[p];
                    #pragma unroll
                    for (int kn = 0; kn < 8; kn++) {
                        const int nn = kn * 16;
                        uint32_t Xh[4], Xl[4];
                        ldsm4(Xh, sptr(&xh[(16 * hw + lr) * XP + nn + lh * 8]));
                        ldsm4(Xl, sptr(&xl[(16 * hw + lr) * XP + nn + lh * 8]));
                        uint32_t b0h[4], b0l[4], b1h[4], b1l[4];
                        ldsm4(b0h, sptr(&s.ahi[brow * AP + nn + bcol]));
                        ldsm4(b0l, sptr(&s.alo[brow * AP + nn + bcol]));
                        ldsm4(b1h, sptr(&s.ahi[(16 + brow) * AP + nn + bcol]));
                        ldsm4(b1l, sptr(&s.alo[(16 + brow) * AP + nn + bcol]));
                        mma16816(e[0], Xh, b0h + 0); mma16816(e[0], Xh, b0l + 0); mma16816(e[0], Xl, b0h + 0);
                        mma16816(e[1], Xh, b0h + 2); mma16816(e[1], Xh, b0l + 2); mma16816(e[1], Xl, b0h + 2);
                        mma16816(e[2], Xh, b1h + 0); mma16816(e[2], Xh, b1l + 0); mma16816(e[2], Xl, b1h + 0);
                        mma16816(e[3], Xh, b1h + 2); mma16816(e[3], Xh, b1l + 2); mma16816(e[3], Xl, b1h + 2);
                    }
                } else {
                    // ---- light: S_k partial from bf16 A (register accumulate) ----
                    const __nv_bfloat162* row =
                        reinterpret_cast<const __nv_bfloat162*>(&s.ahi[kL * AP + segL * 32]);
                    float tS = 0.f;
                    #pragma unroll
                    for (int j = 0; j < 16; j++) {
                        float2 f2 = __bfloat1622float2(row[j]);
                        tS += f2.x + f2.y;
                    }
                    Sreg += tS;
                }
                bararrive(2 + p, 512);                     // signal buffer empty
                p ^= 1;
            }
            // ---- unit epilogue ----
            if (!heavy) { s.Spart[lslot] = Sreg; Sreg = 0.f; }
            barsync(4, 384);
            if (heavy) {
                float* outb = out + (size_t)(u >> 5) * (32 * 128);
                #pragma unroll
                for (int j = 0; j < 4; j++) {
                    const int k0 = j * 8 + 2 * t, d0 = 16 * hw + g;
                    const float S0 = s.Spart[k0] + s.Spart[32 + k0] + s.Spart[64 + k0] + s.Spart[96 + k0];
                    const float S1 = s.Spart[k0 + 1] + s.Spart[33 + k0] + s.Spart[65 + k0] + s.Spart[97 + k0];
                    atomicAdd(&outb[k0 * 128 + d0],            e[j][0] - S0 * Cg[k0 * 128 + d0]);
                    atomicAdd(&outb[(k0 + 1) * 128 + d0],      e[j][1] - S1 * Cg[(k0 + 1) * 128 + d0]);
                    atomicAdd(&outb[k0 * 128 + d0 + 8],        e[j][2] - S0 * Cg[k0 * 128 + d0 + 8]);
                    atomicAdd(&outb[(k0 + 1) * 128 + d0 + 8],  e[j][3] - S1 * Cg[(k0 + 1) * 128 + d0 + 8]);
                    e[j][0] = 0.f; e[j][1] = 0.f; e[j][2] = 0.f; e[j][3] = 0.f;
                }
            }
        }
    }
}

extern "C" void kernel_launch(void* const* d_in, const int* in_sizes, int n_in,
                              void* d_out, int out_size) {
    const float* X  = (const float*)d_in[0];
    const float* C  = (const float*)d_in[1];
    const float* sc = (const float*)d_in[2];
    float* out = (float*)d_out;

    int dev = 0, sms = 0;
    cudaGetDevice(&dev);
    cudaDeviceGetAttribute(&sms, cudaDevAttrMultiProcessorCount, dev);
    if (sms <= 0) sms = 148;

    cudaFuncSetAttribute(enc_kernel, cudaFuncAttributeMaxDynamicSharedMemorySize,
                         (int)sizeof(Sm));
    cudaMemsetAsync(out, 0, (size_t)out_size * sizeof(float));
    enc_kernel<<<sms, 512, sizeof(Sm)>>>(X, C, sc, out);
}